// round 11
// baseline (speedup 1.0000x reference)
#include <cuda_runtime.h>
#include <cuda_bf16.h>
#include <cfloat>

#define NN 32
#define CC 256
#define HH 56
#define WW 56
#define HWX 3136
#define NQ4 784          // HWX / 4
#define MIP 8

// Scratch (device globals; no allocation allowed)
__device__ float d_PH[2][NN*CC*HH];   // [branch][n*C+c][h]  row pool (mean=0, max=1)
__device__ float d_PW[2][NN*CC*WW];   // col pool
__device__ float d_AH[2][NN*CC*HH];   // attention h-vector per branch
__device__ float d_AW[2][NN*CC*WW];
__device__ float d_gap[NN*CC];
__device__ float d_g[NN*2];
__device__ float d_om[NN*CC];
__device__ float d_s[NN*CC];

// ---------------------------------------------------------------------------
// Kernel 1: per (n,c) slice (56x56): row mean/max, col mean/max, global mean.
// Strategy: coalesced float4 load of slice into padded smem tile, then
// row threads (0..55) and col threads (64..119) reduce from smem in parallel.
// ---------------------------------------------------------------------------
__global__ __launch_bounds__(256) void k_pool(const float* __restrict__ x) {
    int blk = blockIdx.x;                       // n*C + c
    const float4* xs4 = (const float4*)(x + (size_t)blk * HWX);
    int tid = threadIdx.x;

    __shared__ float tile[HH][57];              // padded: stride 57 (odd) -> conflict-free
    __shared__ float s_row[HH];

    #pragma unroll
    for (int q = tid; q < NQ4; q += 256) {
        float4 v = xs4[q];
        int h = q / 14;
        int w = (q - h * 14) * 4;
        tile[h][w + 0] = v.x;
        tile[h][w + 1] = v.y;
        tile[h][w + 2] = v.z;
        tile[h][w + 3] = v.w;
    }
    __syncthreads();

    if (tid < 56) {                             // row reductions, h = tid
        float rs = 0.f, rm = -FLT_MAX;
        #pragma unroll
        for (int w = 0; w < 56; w++) {
            float v = tile[tid][w];
            rs += v;
            rm = fmaxf(rm, v);
        }
        d_PH[0][blk * HH + tid] = rs * (1.f / 56.f);
        d_PH[1][blk * HH + tid] = rm;
        s_row[tid] = rs;
    } else if (tid >= 64 && tid < 120) {        // col reductions, w = tid-64
        int w = tid - 64;
        float cs = 0.f, cm = -FLT_MAX;
        #pragma unroll
        for (int h = 0; h < 56; h++) {
            float v = tile[h][w];
            cs += v;
            cm = fmaxf(cm, v);
        }
        d_PW[0][blk * WW + w] = cs * (1.f / 56.f);
        d_PW[1][blk * WW + w] = cm;
    }
    __syncthreads();
    if (tid == 0) {
        float t = 0.f;
        #pragma unroll
        for (int h = 0; h < 56; h++) t += s_row[h];
        d_gap[blk] = t * (1.f / 3136.f);
    }
}

// ---------------------------------------------------------------------------
// Kernel 2: per (branch, n): y = BN(w1 @ pool) -> relu, then
// ah = sigmoid(wh @ yh), aw = sigmoid(ww @ yw). 64 blocks x 128 threads.
// ---------------------------------------------------------------------------
__global__ __launch_bounds__(128) void k_branch(
    const float* __restrict__ w1, const float* __restrict__ b1,
    const float* __restrict__ gamma, const float* __restrict__ beta,
    const float* __restrict__ rmean, const float* __restrict__ rvar,
    const float* __restrict__ wh, const float* __restrict__ bh,
    const float* __restrict__ ww, const float* __restrict__ bw)
{
    int b = blockIdx.x >> 5;        // branch (0=mean,1=max)
    int n = blockIdx.x & 31;
    int tid = threadIdx.x;

    __shared__ float s_w1[MIP * CC];
    __shared__ float s_wh[CC * MIP];
    __shared__ float s_ww[CC * MIP];
    __shared__ float s_y[MIP][112];
    __shared__ float s_scale[MIP], s_shift[MIP];

    for (int i = tid; i < MIP * CC; i += 128) {
        s_w1[i] = w1[i]; s_wh[i] = wh[i]; s_ww[i] = ww[i];
    }
    if (tid < MIP) {
        float sc = gamma[tid] * rsqrtf(rvar[tid] + 1e-5f);
        s_scale[tid] = sc;
        s_shift[tid] = beta[tid] + (b1[tid] - rmean[tid]) * sc;
    }
    __syncthreads();

    if (tid < 112) {
        float acc[MIP];
        #pragma unroll
        for (int m = 0; m < MIP; m++) acc[m] = 0.f;
        const float* P0 = (tid < HH) ? &d_PH[b][(n * CC) * HH + tid]
                                     : &d_PW[b][(n * CC) * WW + (tid - HH)];
        for (int c = 0; c < CC; c++) {
            float p = P0[c * HH];
            #pragma unroll
            for (int m = 0; m < MIP; m++) acc[m] += s_w1[m * CC + c] * p;
        }
        #pragma unroll
        for (int m = 0; m < MIP; m++)
            s_y[m][tid] = fmaxf(acc[m] * s_scale[m] + s_shift[m], 0.f);
    }
    __syncthreads();

    for (int idx = tid; idx < CC * 112; idx += 128) {
        int o = idx / 112, l = idx - o * 112;
        const float* wv = (l < HH) ? &s_wh[o * MIP] : &s_ww[o * MIP];
        float a = (l < HH) ? bh[o] : bw[o];
        #pragma unroll
        for (int m = 0; m < MIP; m++) a += wv[m] * s_y[m][l];
        a = 1.f / (1.f + __expf(-a));
        if (l < HH) d_AH[b][(n * CC + o) * HH + l] = a;
        else        d_AW[b][(n * CC + o) * WW + (l - HH)] = a;
    }
}

// ---------------------------------------------------------------------------
// Kernel 3: gating softmax g[n][2]. 32 blocks x 64 threads.
// ---------------------------------------------------------------------------
__global__ __launch_bounds__(64) void k_gate(
    const float* __restrict__ gw1, const float* __restrict__ gw2,
    const float* __restrict__ gb2)
{
    int n = blockIdx.x, tid = threadIdx.x;
    __shared__ float s_gap[CC], s_t[64];
    for (int i = tid; i < CC; i += 64) s_gap[i] = d_gap[n * CC + i];
    __syncthreads();
    float a = 0.f;
    const float* wr = gw1 + tid * CC;
    for (int c = 0; c < CC; c++) a += wr[c] * s_gap[c];
    s_t[tid] = fmaxf(a, 0.f);
    __syncthreads();
    if (tid == 0) {
        float l0 = gb2[0], l1 = gb2[1];
        #pragma unroll
        for (int j = 0; j < 64; j++) {
            l0 += gw2[j] * s_t[j];
            l1 += gw2[64 + j] * s_t[j];
        }
        float mx = fmaxf(l0, l1);
        float e0 = __expf(l0 - mx), e1 = __expf(l1 - mx);
        float inv = 1.f / (e0 + e1);
        d_g[n * 2 + 0] = e0 * inv;
        d_g[n * 2 + 1] = e1 * inv;
    }
}

// ---------------------------------------------------------------------------
// Kernel 4: omean[n][c] = mean_{h,w}( x * attn ). Block per (n,c), float4.
// attn[h][w] = ah0[h]*awm[w] + ah1[h]*awx[w]  (g gate folded into ah).
// ---------------------------------------------------------------------------
__global__ __launch_bounds__(256) void k_osum(const float* __restrict__ x) {
    int blk = blockIdx.x;
    int n = blk >> 8;
    const float4* xs4 = (const float4*)(x + (size_t)blk * HWX);
    __shared__ float ah0[HH], ah1[HH], awm[WW], awx[WW];
    int tid = threadIdx.x;
    if (tid < 56) {
        float g0 = d_g[n * 2], g1 = d_g[n * 2 + 1];
        ah0[tid] = g0 * d_AH[0][blk * HH + tid];
        ah1[tid] = g1 * d_AH[1][blk * HH + tid];
        awm[tid] = d_AW[0][blk * WW + tid];
        awx[tid] = d_AW[1][blk * WW + tid];
    }
    __syncthreads();
    float acc = 0.f;
    #pragma unroll
    for (int q = tid; q < NQ4; q += 256) {
        float4 v = xs4[q];
        int h = q / 14;
        int w = (q - h * 14) * 4;
        float a0 = ah0[h], a1 = ah1[h];
        acc += v.x * (a0 * awm[w + 0] + a1 * awx[w + 0]);
        acc += v.y * (a0 * awm[w + 1] + a1 * awx[w + 1]);
        acc += v.z * (a0 * awm[w + 2] + a1 * awx[w + 2]);
        acc += v.w * (a0 * awm[w + 3] + a1 * awx[w + 3]);
    }
    #pragma unroll
    for (int o = 16; o; o >>= 1) acc += __shfl_down_sync(0xFFFFFFFFu, acc, o);
    __shared__ float s_p[8];
    if ((tid & 31) == 0) s_p[tid >> 5] = acc;
    __syncthreads();
    if (tid == 0) {
        float t = 0.f;
        #pragma unroll
        for (int i = 0; i < 8; i++) t += s_p[i];
        d_om[blk] = t * (1.f / 3136.f);
    }
}

// ---------------------------------------------------------------------------
// Kernel 5: SE sigmoid s[n][c]. 32 blocks x 64 threads.
// ---------------------------------------------------------------------------
__global__ __launch_bounds__(64) void k_se(
    const float* __restrict__ cw1, const float* __restrict__ cw2,
    const float* __restrict__ cb2)
{
    int n = blockIdx.x, tid = threadIdx.x;
    __shared__ float s_o[CC], s_t[64];
    for (int i = tid; i < CC; i += 64) s_o[i] = d_om[n * CC + i];
    __syncthreads();
    float a = 0.f;
    const float* wr = cw1 + tid * CC;
    for (int c = 0; c < CC; c++) a += wr[c] * s_o[c];
    s_t[tid] = fmaxf(a, 0.f);
    __syncthreads();
    for (int c = tid; c < CC; c += 64) {
        float b = cb2[c];
        const float* w2 = cw2 + c * 64;
        #pragma unroll
        for (int j = 0; j < 64; j++) b += w2[j] * s_t[j];
        d_s[n * CC + c] = 1.f / (1.f + __expf(-b));
    }
}

// ---------------------------------------------------------------------------
// Kernel 6: out = x * (attn*s + 1). Block per (n,c), float4 in/out.
// ---------------------------------------------------------------------------
__global__ __launch_bounds__(256) void k_final(const float* __restrict__ x,
                                               float* __restrict__ out) {
    int blk = blockIdx.x;
    int n = blk >> 8;
    const float4* xs4 = (const float4*)(x + (size_t)blk * HWX);
    float4* os4 = (float4*)(out + (size_t)blk * HWX);
    __shared__ float a1[HH], a3[HH], awm[WW], awx[WW];
    int tid = threadIdx.x;
    if (tid < 56) {
        float g0 = d_g[n * 2], g1 = d_g[n * 2 + 1], s = d_s[blk];
        a1[tid]  = g0 * s * d_AH[0][blk * HH + tid];
        a3[tid]  = g1 * s * d_AH[1][blk * HH + tid];
        awm[tid] = d_AW[0][blk * WW + tid];
        awx[tid] = d_AW[1][blk * WW + tid];
    }
    __syncthreads();
    #pragma unroll
    for (int q = tid; q < NQ4; q += 256) {
        float4 v = xs4[q];
        int h = q / 14;
        int w = (q - h * 14) * 4;
        float b0 = a1[h], b1 = a3[h];
        float4 r;
        r.x = v.x * (b0 * awm[w + 0] + b1 * awx[w + 0] + 1.f);
        r.y = v.y * (b0 * awm[w + 1] + b1 * awx[w + 1] + 1.f);
        r.z = v.z * (b0 * awm[w + 2] + b1 * awx[w + 2] + 1.f);
        r.w = v.w * (b0 * awm[w + 3] + b1 * awx[w + 3] + 1.f);
        os4[q] = r;
    }
}

extern "C" void kernel_launch(void* const* d_in, const int* in_sizes, int n_in,
                              void* d_out, int out_size) {
    const float* x     = (const float*)d_in[0];
    const float* w1    = (const float*)d_in[1];
    const float* b1    = (const float*)d_in[2];
    const float* gamma = (const float*)d_in[3];
    const float* beta  = (const float*)d_in[4];
    const float* rmean = (const float*)d_in[5];
    const float* rvar  = (const float*)d_in[6];
    const float* wh    = (const float*)d_in[7];
    const float* bh    = (const float*)d_in[8];
    const float* ww    = (const float*)d_in[9];
    const float* bw    = (const float*)d_in[10];
    const float* gw1   = (const float*)d_in[11];
    const float* gw2   = (const float*)d_in[12];
    const float* gb2   = (const float*)d_in[13];
    const float* cw1   = (const float*)d_in[14];
    const float* cw2   = (const float*)d_in[15];
    const float* cb2   = (const float*)d_in[16];
    float* out = (float*)d_out;

    k_pool<<<NN * CC, 256>>>(x);
    k_branch<<<64, 128>>>(w1, b1, gamma, beta, rmean, rvar, wh, bh, ww, bw);
    k_gate<<<NN, 64>>>(gw1, gw2, gb2);
    k_osum<<<NN * CC, 256>>>(x);
    k_se<<<NN, 64>>>(cw1, cw2, cb2);
    k_final<<<NN * CC, 256>>>(x, out);
}

// round 12
// speedup vs baseline: 1.1436x; 1.1436x over previous
#include <cuda_runtime.h>
#include <cuda_bf16.h>
#include <cfloat>

#define NN 32
#define CC 256
#define HH 56
#define WW 56
#define HWX 3136
#define NQ4 784          // HWX / 4
#define MIP 8
#define LL 112           // HH + WW

// Scratch (device globals; no allocation allowed)
// Pools, transposed for contiguous k_branch reads: [branch][n][l][c]
__device__ float d_PT[2][NN * LL * CC];
// Attention vectors: [branch][n][c][l]  (l<56: ah, l>=56: aw)
__device__ float d_A[2][NN * CC * LL];
__device__ float d_gap[NN * CC];
__device__ float d_g[NN * 2];
__device__ float d_om[NN * CC];
__device__ float d_s[NN * CC];

// ---------------------------------------------------------------------------
// Kernel 1: per (n,c) slice: row mean/max, col mean/max, global mean.
// Front-batched float4 loads -> padded smem tile -> parallel row/col reduce.
// ---------------------------------------------------------------------------
__global__ __launch_bounds__(256) void k_pool(const float* __restrict__ x) {
    int blk = blockIdx.x;                       // n*C + c
    int n = blk >> 8, c = blk & 255;
    const float4* xs4 = (const float4*)(x + (size_t)blk * HWX);
    int tid = threadIdx.x;

    __shared__ float tile[HH][57];
    __shared__ float s_row[HH];

    // Front-batch all global loads (MLP=4, no loop carry)
    float4 v0 = xs4[tid];
    float4 v1 = xs4[tid + 256];
    float4 v2 = xs4[tid + 512];
    float4 v3;
    if (tid < 16) v3 = xs4[tid + 768];

    {
        int q, h, w;
        q = tid;        h = q / 14; w = (q - h * 14) * 4;
        tile[h][w] = v0.x; tile[h][w+1] = v0.y; tile[h][w+2] = v0.z; tile[h][w+3] = v0.w;
        q = tid + 256;  h = q / 14; w = (q - h * 14) * 4;
        tile[h][w] = v1.x; tile[h][w+1] = v1.y; tile[h][w+2] = v1.z; tile[h][w+3] = v1.w;
        q = tid + 512;  h = q / 14; w = (q - h * 14) * 4;
        tile[h][w] = v2.x; tile[h][w+1] = v2.y; tile[h][w+2] = v2.z; tile[h][w+3] = v2.w;
        if (tid < 16) {
            q = tid + 768; h = q / 14; w = (q - h * 14) * 4;
            tile[h][w] = v3.x; tile[h][w+1] = v3.y; tile[h][w+2] = v3.z; tile[h][w+3] = v3.w;
        }
    }
    __syncthreads();

    if (tid < 56) {                             // row reduce, h = tid, l = tid
        float rs = 0.f, rm = -FLT_MAX;
        #pragma unroll
        for (int w = 0; w < 56; w++) {
            float v = tile[tid][w];
            rs += v; rm = fmaxf(rm, v);
        }
        d_PT[0][(n * LL + tid) * CC + c] = rs * (1.f / 56.f);
        d_PT[1][(n * LL + tid) * CC + c] = rm;
        s_row[tid] = rs;
    } else if (tid >= 64 && tid < 120) {        // col reduce, w = tid-64, l = 56+w
        int w = tid - 64;
        float cs = 0.f, cm = -FLT_MAX;
        #pragma unroll
        for (int h = 0; h < 56; h++) {
            float v = tile[h][w];
            cs += v; cm = fmaxf(cm, v);
        }
        d_PT[0][(n * LL + 56 + w) * CC + c] = cs * (1.f / 56.f);
        d_PT[1][(n * LL + 56 + w) * CC + c] = cm;
    }
    __syncthreads();
    if (tid == 0) {
        float t = 0.f;
        #pragma unroll
        for (int h = 0; h < 56; h++) t += s_row[h];
        d_gap[blk] = t * (1.f / 3136.f);
    }
}

// ---------------------------------------------------------------------------
// Kernel 2: blocks 0..63 -> branch MLP per (branch,n); blocks 64..95 -> gate.
// ---------------------------------------------------------------------------
__global__ __launch_bounds__(128) void k_branch(
    const float* __restrict__ w1, const float* __restrict__ b1,
    const float* __restrict__ gamma, const float* __restrict__ beta,
    const float* __restrict__ rmean, const float* __restrict__ rvar,
    const float* __restrict__ wh, const float* __restrict__ bh,
    const float* __restrict__ ww, const float* __restrict__ bw,
    const float* __restrict__ gw1, const float* __restrict__ gw2,
    const float* __restrict__ gb2)
{
    int tid = threadIdx.x;

    if (blockIdx.x >= 64) {                     // ---- gate path ----
        int n = blockIdx.x - 64;
        __shared__ float s_gap[CC], s_t[64];
        for (int i = tid; i < CC; i += 128) s_gap[i] = d_gap[n * CC + i];
        __syncthreads();
        if (tid < 64) {
            float a = 0.f;
            const float* wr = gw1 + tid * CC;
            for (int c = 0; c < CC; c++) a += wr[c] * s_gap[c];
            s_t[tid] = fmaxf(a, 0.f);
        }
        __syncthreads();
        if (tid == 0) {
            float l0 = gb2[0], l1 = gb2[1];
            #pragma unroll
            for (int j = 0; j < 64; j++) {
                l0 += gw2[j] * s_t[j];
                l1 += gw2[64 + j] * s_t[j];
            }
            float mx = fmaxf(l0, l1);
            float e0 = __expf(l0 - mx), e1 = __expf(l1 - mx);
            float inv = 1.f / (e0 + e1);
            d_g[n * 2 + 0] = e0 * inv;
            d_g[n * 2 + 1] = e1 * inv;
        }
        return;
    }

    // ---- branch path ----
    int b = blockIdx.x >> 5;        // branch (0=mean,1=max)
    int n = blockIdx.x & 31;

    __shared__ float s_w1[MIP * CC];
    __shared__ float s_wh[CC * MIP];
    __shared__ float s_ww[CC * MIP];
    __shared__ float s_y[MIP][LL];
    __shared__ float s_scale[MIP], s_shift[MIP];

    for (int i = tid; i < MIP * CC; i += 128) {
        s_w1[i] = w1[i]; s_wh[i] = wh[i]; s_ww[i] = ww[i];
    }
    if (tid < MIP) {
        float sc = gamma[tid] * rsqrtf(rvar[tid] + 1e-5f);
        s_scale[tid] = sc;
        s_shift[tid] = beta[tid] + (b1[tid] - rmean[tid]) * sc;
    }
    __syncthreads();

    if (tid < LL) {
        float acc[MIP];
        #pragma unroll
        for (int m = 0; m < MIP; m++) acc[m] = 0.f;
        const float4* P4 = (const float4*)&d_PT[b][(n * LL + tid) * CC];
        #pragma unroll 4
        for (int c4 = 0; c4 < CC / 4; c4++) {
            float4 p = P4[c4];
            int c = c4 * 4;
            #pragma unroll
            for (int m = 0; m < MIP; m++) {
                acc[m] += s_w1[m * CC + c + 0] * p.x;
                acc[m] += s_w1[m * CC + c + 1] * p.y;
                acc[m] += s_w1[m * CC + c + 2] * p.z;
                acc[m] += s_w1[m * CC + c + 3] * p.w;
            }
        }
        #pragma unroll
        for (int m = 0; m < MIP; m++)
            s_y[m][tid] = fmaxf(acc[m] * s_scale[m] + s_shift[m], 0.f);
    }
    __syncthreads();

    for (int idx = tid; idx < CC * LL; idx += 128) {
        int o = idx / LL, l = idx - o * LL;
        const float* wv = (l < HH) ? &s_wh[o * MIP] : &s_ww[o * MIP];
        float a = (l < HH) ? bh[o] : bw[o];
        #pragma unroll
        for (int m = 0; m < MIP; m++) a += wv[m] * s_y[m][l];
        d_A[b][(n * CC + o) * LL + l] = 1.f / (1.f + __expf(-a));
    }
}

// ---------------------------------------------------------------------------
// Kernel 3: omean[n][c] = mean_{h,w}( x * attn ). Block per (n,c), float4,
// front-batched loads overlapping the smem/barrier phase.
// ---------------------------------------------------------------------------
__global__ __launch_bounds__(256) void k_osum(const float* __restrict__ x) {
    int blk = blockIdx.x;
    int n = blk >> 8;
    const float4* xs4 = (const float4*)(x + (size_t)blk * HWX);
    int tid = threadIdx.x;

    // issue global loads first (independent of smem phase)
    float4 v0 = xs4[tid];
    float4 v1 = xs4[tid + 256];
    float4 v2 = xs4[tid + 512];
    float4 v3;
    if (tid < 16) v3 = xs4[tid + 768];

    __shared__ float ah0[HH], ah1[HH], awm[WW], awx[WW];
    if (tid < 56) {
        float g0 = d_g[n * 2], g1 = d_g[n * 2 + 1];
        ah0[tid] = g0 * d_A[0][blk * LL + tid];
        ah1[tid] = g1 * d_A[1][blk * LL + tid];
        awm[tid] = d_A[0][blk * LL + 56 + tid];
        awx[tid] = d_A[1][blk * LL + 56 + tid];
    }
    __syncthreads();

    float acc = 0.f;
    {
        int q, h, w; float a0, a1;
        q = tid;       h = q / 14; w = (q - h * 14) * 4; a0 = ah0[h]; a1 = ah1[h];
        acc += v0.x * (a0 * awm[w+0] + a1 * awx[w+0]);
        acc += v0.y * (a0 * awm[w+1] + a1 * awx[w+1]);
        acc += v0.z * (a0 * awm[w+2] + a1 * awx[w+2]);
        acc += v0.w * (a0 * awm[w+3] + a1 * awx[w+3]);
        q = tid + 256; h = q / 14; w = (q - h * 14) * 4; a0 = ah0[h]; a1 = ah1[h];
        acc += v1.x * (a0 * awm[w+0] + a1 * awx[w+0]);
        acc += v1.y * (a0 * awm[w+1] + a1 * awx[w+1]);
        acc += v1.z * (a0 * awm[w+2] + a1 * awx[w+2]);
        acc += v1.w * (a0 * awm[w+3] + a1 * awx[w+3]);
        q = tid + 512; h = q / 14; w = (q - h * 14) * 4; a0 = ah0[h]; a1 = ah1[h];
        acc += v2.x * (a0 * awm[w+0] + a1 * awx[w+0]);
        acc += v2.y * (a0 * awm[w+1] + a1 * awx[w+1]);
        acc += v2.z * (a0 * awm[w+2] + a1 * awx[w+2]);
        acc += v2.w * (a0 * awm[w+3] + a1 * awx[w+3]);
        if (tid < 16) {
            q = tid + 768; h = q / 14; w = (q - h * 14) * 4; a0 = ah0[h]; a1 = ah1[h];
            acc += v3.x * (a0 * awm[w+0] + a1 * awx[w+0]);
            acc += v3.y * (a0 * awm[w+1] + a1 * awx[w+1]);
            acc += v3.z * (a0 * awm[w+2] + a1 * awx[w+2]);
            acc += v3.w * (a0 * awm[w+3] + a1 * awx[w+3]);
        }
    }
    #pragma unroll
    for (int o = 16; o; o >>= 1) acc += __shfl_down_sync(0xFFFFFFFFu, acc, o);
    __shared__ float s_p[8];
    if ((tid & 31) == 0) s_p[tid >> 5] = acc;
    __syncthreads();
    if (tid == 0) {
        float t = 0.f;
        #pragma unroll
        for (int i = 0; i < 8; i++) t += s_p[i];
        d_om[blk] = t * (1.f / 3136.f);
    }
}

// ---------------------------------------------------------------------------
// Kernel 4: SE sigmoid s[n][c]. 32 blocks x 64 threads.
// ---------------------------------------------------------------------------
__global__ __launch_bounds__(64) void k_se(
    const float* __restrict__ cw1, const float* __restrict__ cw2,
    const float* __restrict__ cb2)
{
    int n = blockIdx.x, tid = threadIdx.x;
    __shared__ float s_o[CC], s_t[64];
    for (int i = tid; i < CC; i += 64) s_o[i] = d_om[n * CC + i];
    __syncthreads();
    float a = 0.f;
    const float* wr = cw1 + tid * CC;
    for (int c = 0; c < CC; c++) a += wr[c] * s_o[c];
    s_t[tid] = fmaxf(a, 0.f);
    __syncthreads();
    for (int c = tid; c < CC; c += 64) {
        float b = cb2[c];
        const float* w2 = cw2 + c * 64;
        #pragma unroll
        for (int j = 0; j < 64; j++) b += w2[j] * s_t[j];
        d_s[n * CC + c] = 1.f / (1.f + __expf(-b));
    }
}

// ---------------------------------------------------------------------------
// Kernel 5: out = x * (attn*s + 1). Block per (n,c), batched float4 in/out.
// ---------------------------------------------------------------------------
__global__ __launch_bounds__(256) void k_final(const float* __restrict__ x,
                                               float* __restrict__ out) {
    int blk = blockIdx.x;
    int n = blk >> 8;
    const float4* xs4 = (const float4*)(x + (size_t)blk * HWX);
    float4* os4 = (float4*)(out + (size_t)blk * HWX);
    int tid = threadIdx.x;

    float4 v0 = xs4[tid];
    float4 v1 = xs4[tid + 256];
    float4 v2 = xs4[tid + 512];
    float4 v3;
    if (tid < 16) v3 = xs4[tid + 768];

    __shared__ float a1[HH], a3[HH], awm[WW], awx[WW];
    if (tid < 56) {
        float g0 = d_g[n * 2], g1 = d_g[n * 2 + 1], s = d_s[blk];
        a1[tid]  = g0 * s * d_A[0][blk * LL + tid];
        a3[tid]  = g1 * s * d_A[1][blk * LL + tid];
        awm[tid] = d_A[0][blk * LL + 56 + tid];
        awx[tid] = d_A[1][blk * LL + 56 + tid];
    }
    __syncthreads();

    {
        int q, h, w; float b0, b1; float4 r;
        q = tid;       h = q / 14; w = (q - h * 14) * 4; b0 = a1[h]; b1 = a3[h];
        r.x = v0.x * (b0 * awm[w+0] + b1 * awx[w+0] + 1.f);
        r.y = v0.y * (b0 * awm[w+1] + b1 * awx[w+1] + 1.f);
        r.z = v0.z * (b0 * awm[w+2] + b1 * awx[w+2] + 1.f);
        r.w = v0.w * (b0 * awm[w+3] + b1 * awx[w+3] + 1.f);
        os4[q] = r;
        q = tid + 256; h = q / 14; w = (q - h * 14) * 4; b0 = a1[h]; b1 = a3[h];
        r.x = v1.x * (b0 * awm[w+0] + b1 * awx[w+0] + 1.f);
        r.y = v1.y * (b0 * awm[w+1] + b1 * awx[w+1] + 1.f);
        r.z = v1.z * (b0 * awm[w+2] + b1 * awx[w+2] + 1.f);
        r.w = v1.w * (b0 * awm[w+3] + b1 * awx[w+3] + 1.f);
        os4[q] = r;
        q = tid + 512; h = q / 14; w = (q - h * 14) * 4; b0 = a1[h]; b1 = a3[h];
        r.x = v2.x * (b0 * awm[w+0] + b1 * awx[w+0] + 1.f);
        r.y = v2.y * (b0 * awm[w+1] + b1 * awx[w+1] + 1.f);
        r.z = v2.z * (b0 * awm[w+2] + b1 * awx[w+2] + 1.f);
        r.w = v2.w * (b0 * awm[w+3] + b1 * awx[w+3] + 1.f);
        os4[q] = r;
        if (tid < 16) {
            q = tid + 768; h = q / 14; w = (q - h * 14) * 4; b0 = a1[h]; b1 = a3[h];
            r.x = v3.x * (b0 * awm[w+0] + b1 * awx[w+0] + 1.f);
            r.y = v3.y * (b0 * awm[w+1] + b1 * awx[w+1] + 1.f);
            r.z = v3.z * (b0 * awm[w+2] + b1 * awx[w+2] + 1.f);
            r.w = v3.w * (b0 * awm[w+3] + b1 * awx[w+3] + 1.f);
            os4[q] = r;
        }
    }
}

extern "C" void kernel_launch(void* const* d_in, const int* in_sizes, int n_in,
                              void* d_out, int out_size) {
    const float* x     = (const float*)d_in[0];
    const float* w1    = (const float*)d_in[1];
    const float* b1    = (const float*)d_in[2];
    const float* gamma = (const float*)d_in[3];
    const float* beta  = (const float*)d_in[4];
    const float* rmean = (const float*)d_in[5];
    const float* rvar  = (const float*)d_in[6];
    const float* wh    = (const float*)d_in[7];
    const float* bh    = (const float*)d_in[8];
    const float* ww    = (const float*)d_in[9];
    const float* bw    = (const float*)d_in[10];
    const float* gw1   = (const float*)d_in[11];
    const float* gw2   = (const float*)d_in[12];
    const float* gb2   = (const float*)d_in[13];
    const float* cw1   = (const float*)d_in[14];
    const float* cw2   = (const float*)d_in[15];
    const float* cb2   = (const float*)d_in[16];
    float* out = (float*)d_out;

    k_pool<<<NN * CC, 256>>>(x);
    k_branch<<<96, 128>>>(w1, b1, gamma, beta, rmean, rvar, wh, bh, ww, bw,
                          gw1, gw2, gb2);
    k_osum<<<NN * CC, 256>>>(x);
    k_se<<<NN, 64>>>(cw1, cw2, cb2);
    k_final<<<NN * CC, 256>>>(x, out);
}

// round 13
// speedup vs baseline: 1.1566x; 1.0113x over previous
#include <cuda_runtime.h>
#include <cuda_bf16.h>
#include <cfloat>

#define NN 32
#define CC 256
#define HH 56
#define WW 56
#define HWX 3136
#define NQ4 784          // HWX / 4
#define MIP 8
#define LL 112           // HH + WW

// Scratch (device globals; no allocation allowed)
__device__ float d_PT[2][NN * LL * CC];   // pools transposed: [branch][n][l][c]
__device__ float d_A[2][NN * CC * LL];    // attention: [branch][n][c][l]
__device__ float d_gap[NN * CC];
__device__ float d_g[NN * 2];
__device__ float d_om[NN * CC];
__device__ float d_s[NN * CC];
__device__ int   d_cnt[NN];               // per-image completion counters (zero-init, self-resetting)

// ---------------------------------------------------------------------------
// Kernel 1: per (n,c) slice: row mean/max, col mean/max, global mean.
// ---------------------------------------------------------------------------
__global__ __launch_bounds__(256) void k_pool(const float* __restrict__ x) {
    int blk = blockIdx.x;                       // n*C + c
    int n = blk >> 8, c = blk & 255;
    const float4* xs4 = (const float4*)(x + (size_t)blk * HWX);
    int tid = threadIdx.x;

    __shared__ float tile[HH][57];
    __shared__ float s_row[HH];

    float4 v0 = xs4[tid];
    float4 v1 = xs4[tid + 256];
    float4 v2 = xs4[tid + 512];
    float4 v3;
    if (tid < 16) v3 = xs4[tid + 768];

    {
        int q, h, w;
        q = tid;        h = q / 14; w = (q - h * 14) * 4;
        tile[h][w] = v0.x; tile[h][w+1] = v0.y; tile[h][w+2] = v0.z; tile[h][w+3] = v0.w;
        q = tid + 256;  h = q / 14; w = (q - h * 14) * 4;
        tile[h][w] = v1.x; tile[h][w+1] = v1.y; tile[h][w+2] = v1.z; tile[h][w+3] = v1.w;
        q = tid + 512;  h = q / 14; w = (q - h * 14) * 4;
        tile[h][w] = v2.x; tile[h][w+1] = v2.y; tile[h][w+2] = v2.z; tile[h][w+3] = v2.w;
        if (tid < 16) {
            q = tid + 768; h = q / 14; w = (q - h * 14) * 4;
            tile[h][w] = v3.x; tile[h][w+1] = v3.y; tile[h][w+2] = v3.z; tile[h][w+3] = v3.w;
        }
    }
    __syncthreads();

    if (tid < 56) {                             // row reduce, l = tid
        float rs = 0.f, rm = -FLT_MAX;
        #pragma unroll
        for (int w = 0; w < 56; w++) {
            float v = tile[tid][w];
            rs += v; rm = fmaxf(rm, v);
        }
        d_PT[0][(n * LL + tid) * CC + c] = rs * (1.f / 56.f);
        d_PT[1][(n * LL + tid) * CC + c] = rm;
        s_row[tid] = rs;
    } else if (tid >= 64 && tid < 120) {        // col reduce, l = 56 + (tid-64)
        int w = tid - 64;
        float cs = 0.f, cm = -FLT_MAX;
        #pragma unroll
        for (int h = 0; h < 56; h++) {
            float v = tile[h][w];
            cs += v; cm = fmaxf(cm, v);
        }
        d_PT[0][(n * LL + 56 + w) * CC + c] = cs * (1.f / 56.f);
        d_PT[1][(n * LL + 56 + w) * CC + c] = cm;
    }
    __syncthreads();
    if (tid == 0) {
        float t = 0.f;
        #pragma unroll
        for (int h = 0; h < 56; h++) t += s_row[h];
        d_gap[blk] = t * (1.f / 3136.f);
    }
}

// ---------------------------------------------------------------------------
// Kernel 2: blocks 0..63 -> branch MLP per (branch,n); blocks 64..95 -> gate.
// ---------------------------------------------------------------------------
__global__ __launch_bounds__(128) void k_branch(
    const float* __restrict__ w1, const float* __restrict__ b1,
    const float* __restrict__ gamma, const float* __restrict__ beta,
    const float* __restrict__ rmean, const float* __restrict__ rvar,
    const float* __restrict__ wh, const float* __restrict__ bh,
    const float* __restrict__ ww, const float* __restrict__ bw,
    const float* __restrict__ gw1, const float* __restrict__ gw2,
    const float* __restrict__ gb2)
{
    int tid = threadIdx.x;

    if (blockIdx.x >= 64) {                     // ---- gate path ----
        int n = blockIdx.x - 64;
        __shared__ float s_gap[CC], s_t[64];
        for (int i = tid; i < CC; i += 128) s_gap[i] = d_gap[n * CC + i];
        __syncthreads();
        if (tid < 64) {
            float a = 0.f;
            const float4* wr = (const float4*)(gw1 + tid * CC);
            #pragma unroll 8
            for (int c4 = 0; c4 < CC / 4; c4++) {
                float4 w4 = wr[c4];
                int c = c4 * 4;
                a += w4.x * s_gap[c] + w4.y * s_gap[c+1] + w4.z * s_gap[c+2] + w4.w * s_gap[c+3];
            }
            s_t[tid] = fmaxf(a, 0.f);
        }
        __syncthreads();
        if (tid == 0) {
            float l0 = gb2[0], l1 = gb2[1];
            #pragma unroll
            for (int j = 0; j < 64; j++) {
                l0 += gw2[j] * s_t[j];
                l1 += gw2[64 + j] * s_t[j];
            }
            float mx = fmaxf(l0, l1);
            float e0 = __expf(l0 - mx), e1 = __expf(l1 - mx);
            float inv = 1.f / (e0 + e1);
            d_g[n * 2 + 0] = e0 * inv;
            d_g[n * 2 + 1] = e1 * inv;
        }
        return;
    }

    // ---- branch path ----
    int b = blockIdx.x >> 5;        // branch (0=mean,1=max)
    int n = blockIdx.x & 31;

    __shared__ float s_w1[MIP * CC];
    __shared__ float s_wh[CC * MIP];
    __shared__ float s_ww[CC * MIP];
    __shared__ float s_y[MIP][LL];
    __shared__ float s_scale[MIP], s_shift[MIP];

    for (int i = tid; i < MIP * CC; i += 128) {
        s_w1[i] = w1[i]; s_wh[i] = wh[i]; s_ww[i] = ww[i];
    }
    if (tid < MIP) {
        float sc = gamma[tid] * rsqrtf(rvar[tid] + 1e-5f);
        s_scale[tid] = sc;
        s_shift[tid] = beta[tid] + (b1[tid] - rmean[tid]) * sc;
    }
    __syncthreads();

    if (tid < LL) {
        float acc[MIP];
        #pragma unroll
        for (int m = 0; m < MIP; m++) acc[m] = 0.f;
        const float4* P4 = (const float4*)&d_PT[b][(n * LL + tid) * CC];
        #pragma unroll 4
        for (int c4 = 0; c4 < CC / 4; c4++) {
            float4 p = P4[c4];
            int c = c4 * 4;
            #pragma unroll
            for (int m = 0; m < MIP; m++) {
                acc[m] += s_w1[m * CC + c + 0] * p.x;
                acc[m] += s_w1[m * CC + c + 1] * p.y;
                acc[m] += s_w1[m * CC + c + 2] * p.z;
                acc[m] += s_w1[m * CC + c + 3] * p.w;
            }
        }
        #pragma unroll
        for (int m = 0; m < MIP; m++)
            s_y[m][tid] = fmaxf(acc[m] * s_scale[m] + s_shift[m], 0.f);
    }
    __syncthreads();

    for (int idx = tid; idx < CC * LL; idx += 128) {
        int o = idx / LL, l = idx - o * LL;
        const float* wv = (l < HH) ? &s_wh[o * MIP] : &s_ww[o * MIP];
        float a = (l < HH) ? bh[o] : bw[o];
        #pragma unroll
        for (int m = 0; m < MIP; m++) a += wv[m] * s_y[m][l];
        d_A[b][(n * CC + o) * LL + l] = 1.f / (1.f + __expf(-a));
    }
}

// ---------------------------------------------------------------------------
// Kernel 3: omean[n][c] = mean_{h,w}( x * attn ), then the LAST block per
// image n (threadfence-reduction pattern) computes the SE MLP inline:
// s[n][:] = sigmoid(relu(om @ cw1^T) @ cw2^T + cb2).
// ---------------------------------------------------------------------------
__global__ __launch_bounds__(256) void k_osum(const float* __restrict__ x,
                                              const float* __restrict__ cw1,
                                              const float* __restrict__ cw2,
                                              const float* __restrict__ cb2) {
    int blk = blockIdx.x;
    int n = blk >> 8;
    const float4* xs4 = (const float4*)(x + (size_t)blk * HWX);
    int tid = threadIdx.x;

    float4 v0 = xs4[tid];
    float4 v1 = xs4[tid + 256];
    float4 v2 = xs4[tid + 512];
    float4 v3;
    if (tid < 16) v3 = xs4[tid + 768];

    __shared__ float ah0[HH], ah1[HH], awm[WW], awx[WW];
    if (tid < 56) {
        float g0 = d_g[n * 2], g1 = d_g[n * 2 + 1];
        ah0[tid] = g0 * d_A[0][blk * LL + tid];
        ah1[tid] = g1 * d_A[1][blk * LL + tid];
        awm[tid] = d_A[0][blk * LL + 56 + tid];
        awx[tid] = d_A[1][blk * LL + 56 + tid];
    }
    __syncthreads();

    float acc = 0.f;
    {
        int q, h, w; float a0, a1;
        q = tid;       h = q / 14; w = (q - h * 14) * 4; a0 = ah0[h]; a1 = ah1[h];
        acc += v0.x * (a0 * awm[w+0] + a1 * awx[w+0]);
        acc += v0.y * (a0 * awm[w+1] + a1 * awx[w+1]);
        acc += v0.z * (a0 * awm[w+2] + a1 * awx[w+2]);
        acc += v0.w * (a0 * awm[w+3] + a1 * awx[w+3]);
        q = tid + 256; h = q / 14; w = (q - h * 14) * 4; a0 = ah0[h]; a1 = ah1[h];
        acc += v1.x * (a0 * awm[w+0] + a1 * awx[w+0]);
        acc += v1.y * (a0 * awm[w+1] + a1 * awx[w+1]);
        acc += v1.z * (a0 * awm[w+2] + a1 * awx[w+2]);
        acc += v1.w * (a0 * awm[w+3] + a1 * awx[w+3]);
        q = tid + 512; h = q / 14; w = (q - h * 14) * 4; a0 = ah0[h]; a1 = ah1[h];
        acc += v2.x * (a0 * awm[w+0] + a1 * awx[w+0]);
        acc += v2.y * (a0 * awm[w+1] + a1 * awx[w+1]);
        acc += v2.z * (a0 * awm[w+2] + a1 * awx[w+2]);
        acc += v2.w * (a0 * awm[w+3] + a1 * awx[w+3]);
        if (tid < 16) {
            q = tid + 768; h = q / 14; w = (q - h * 14) * 4; a0 = ah0[h]; a1 = ah1[h];
            acc += v3.x * (a0 * awm[w+0] + a1 * awx[w+0]);
            acc += v3.y * (a0 * awm[w+1] + a1 * awx[w+1]);
            acc += v3.z * (a0 * awm[w+2] + a1 * awx[w+2]);
            acc += v3.w * (a0 * awm[w+3] + a1 * awx[w+3]);
        }
    }
    #pragma unroll
    for (int o = 16; o; o >>= 1) acc += __shfl_down_sync(0xFFFFFFFFu, acc, o);
    __shared__ float s_p[8];
    if ((tid & 31) == 0) s_p[tid >> 5] = acc;
    __syncthreads();

    __shared__ bool s_last;
    if (tid == 0) {
        float t = 0.f;
        #pragma unroll
        for (int i = 0; i < 8; i++) t += s_p[i];
        d_om[blk] = t * (1.f / 3136.f);
        __threadfence();                        // publish d_om before counting
        int old = atomicAdd(&d_cnt[n], 1);
        s_last = (old == CC - 1);
    }
    __syncthreads();
    if (!s_last) return;

    // ---- last block for image n: SE MLP with 256 threads ----
    __shared__ float s_o[CC];
    __shared__ float s_part[64][4];
    __shared__ float s_t[64];

    s_o[tid] = d_om[n * CC + tid];              // visible via fence+atomic
    __syncthreads();

    {   // hidden layer: j = tid/4 over channel quarter q = tid%4
        int j = tid >> 2, q = tid & 3;
        const float4* wr = (const float4*)(cw1 + j * CC + q * 64);
        float a = 0.f;
        #pragma unroll
        for (int c4 = 0; c4 < 16; c4++) {
            float4 w4 = wr[c4];
            int c = q * 64 + c4 * 4;
            a += w4.x * s_o[c] + w4.y * s_o[c+1] + w4.z * s_o[c+2] + w4.w * s_o[c+3];
        }
        s_part[j][q] = a;
    }
    __syncthreads();
    if (tid < 64)
        s_t[tid] = fmaxf(s_part[tid][0] + s_part[tid][1] + s_part[tid][2] + s_part[tid][3], 0.f);
    __syncthreads();

    {   // output layer: c = tid
        float b = cb2[tid];
        const float4* w2 = (const float4*)(cw2 + tid * 64);
        #pragma unroll
        for (int j4 = 0; j4 < 16; j4++) {
            float4 w4 = w2[j4];
            int j = j4 * 4;
            b += w4.x * s_t[j] + w4.y * s_t[j+1] + w4.z * s_t[j+2] + w4.w * s_t[j+3];
        }
        d_s[n * CC + tid] = 1.f / (1.f + __expf(-b));
    }
    if (tid == 0) d_cnt[n] = 0;                 // reset for next graph replay
}

// ---------------------------------------------------------------------------
// Kernel 4: out = x * (attn*s + 1). Block per (n,c), batched float4 in/out.
// ---------------------------------------------------------------------------
__global__ __launch_bounds__(256) void k_final(const float* __restrict__ x,
                                               float* __restrict__ out) {
    int blk = blockIdx.x;
    int n = blk >> 8;
    const float4* xs4 = (const float4*)(x + (size_t)blk * HWX);
    float4* os4 = (float4*)(out + (size_t)blk * HWX);
    int tid = threadIdx.x;

    float4 v0 = xs4[tid];
    float4 v1 = xs4[tid + 256];
    float4 v2 = xs4[tid + 512];
    float4 v3;
    if (tid < 16) v3 = xs4[tid + 768];

    __shared__ float a1[HH], a3[HH], awm[WW], awx[WW];
    if (tid < 56) {
        float g0 = d_g[n * 2], g1 = d_g[n * 2 + 1], s = d_s[blk];
        a1[tid]  = g0 * s * d_A[0][blk * LL + tid];
        a3[tid]  = g1 * s * d_A[1][blk * LL + tid];
        awm[tid] = d_A[0][blk * LL + 56 + tid];
        awx[tid] = d_A[1][blk * LL + 56 + tid];
    }
    __syncthreads();

    {
        int q, h, w; float b0, b1; float4 r;
        q = tid;       h = q / 14; w = (q - h * 14) * 4; b0 = a1[h]; b1 = a3[h];
        r.x = v0.x * (b0 * awm[w+0] + b1 * awx[w+0] + 1.f);
        r.y = v0.y * (b0 * awm[w+1] + b1 * awx[w+1] + 1.f);
        r.z = v0.z * (b0 * awm[w+2] + b1 * awx[w+2] + 1.f);
        r.w = v0.w * (b0 * awm[w+3] + b1 * awx[w+3] + 1.f);
        os4[q] = r;
        q = tid + 256; h = q / 14; w = (q - h * 14) * 4; b0 = a1[h]; b1 = a3[h];
        r.x = v1.x * (b0 * awm[w+0] + b1 * awx[w+0] + 1.f);
        r.y = v1.y * (b0 * awm[w+1] + b1 * awx[w+1] + 1.f);
        r.z = v1.z * (b0 * awm[w+2] + b1 * awx[w+2] + 1.f);
        r.w = v1.w * (b0 * awm[w+3] + b1 * awx[w+3] + 1.f);
        os4[q] = r;
        q = tid + 512; h = q / 14; w = (q - h * 14) * 4; b0 = a1[h]; b1 = a3[h];
        r.x = v2.x * (b0 * awm[w+0] + b1 * awx[w+0] + 1.f);
        r.y = v2.y * (b0 * awm[w+1] + b1 * awx[w+1] + 1.f);
        r.z = v2.z * (b0 * awm[w+2] + b1 * awx[w+2] + 1.f);
        r.w = v2.w * (b0 * awm[w+3] + b1 * awx[w+3] + 1.f);
        os4[q] = r;
        if (tid < 16) {
            q = tid + 768; h = q / 14; w = (q - h * 14) * 4; b0 = a1[h]; b1 = a3[h];
            r.x = v3.x * (b0 * awm[w+0] + b1 * awx[w+0] + 1.f);
            r.y = v3.y * (b0 * awm[w+1] + b1 * awx[w+1] + 1.f);
            r.z = v3.z * (b0 * awm[w+2] + b1 * awx[w+2] + 1.f);
            r.w = v3.w * (b0 * awm[w+3] + b1 * awx[w+3] + 1.f);
            os4[q] = r;
        }
    }
}

extern "C" void kernel_launch(void* const* d_in, const int* in_sizes, int n_in,
                              void* d_out, int out_size) {
    const float* x     = (const float*)d_in[0];
    const float* w1    = (const float*)d_in[1];
    const float* b1    = (const float*)d_in[2];
    const float* gamma = (const float*)d_in[3];
    const float* beta  = (const float*)d_in[4];
    const float* rmean = (const float*)d_in[5];
    const float* rvar  = (const float*)d_in[6];
    const float* wh    = (const float*)d_in[7];
    const float* bh    = (const float*)d_in[8];
    const float* ww    = (const float*)d_in[9];
    const float* bw    = (const float*)d_in[10];
    const float* gw1   = (const float*)d_in[11];
    const float* gw2   = (const float*)d_in[12];
    const float* gb2   = (const float*)d_in[13];
    const float* cw1   = (const float*)d_in[14];
    const float* cw2   = (const float*)d_in[15];
    const float* cb2   = (const float*)d_in[16];
    float* out = (float*)d_out;

    k_pool<<<NN * CC, 256>>>(x);
    k_branch<<<96, 128>>>(w1, b1, gamma, beta, rmean, rvar, wh, bh, ww, bw,
                          gw1, gw2, gb2);
    k_osum<<<NN * CC, 256>>>(x, cw1, cw2, cb2);
    k_final<<<NN * CC, 256>>>(x, out);
}